// round 13
// baseline (speedup 1.0000x reference)
#include <cuda_runtime.h>
#include <cuda_bf16.h>
#include <cstdint>

#define NEG_INF (-3.402823466e38f)

constexpr int Bc = 16, LQ = 2048, LK = 2048, DD = 1024;

// Static device scratch (sanctioned alloc-free path)
__device__ float g_S[(size_t)Bc * LQ * LK];                                  // 268 MB
__device__ __nv_bfloat16 g_Qh[(size_t)Bc * LQ * DD], g_Ql[(size_t)Bc * LQ * DD];
__device__ __nv_bfloat16 g_Kh[(size_t)Bc * LK * DD], g_Kl[(size_t)Bc * LK * DD];
__device__ __nv_bfloat16 g_Vth[(size_t)Bc * DD * LK], g_Vtl[(size_t)Bc * DD * LK];
__device__ __nv_bfloat16 g_Ph[(size_t)Bc * LQ * LK], g_Pl[(size_t)Bc * LQ * LK];

// ---------------------------------------------------------------------------
// Base-ISA helpers
// ---------------------------------------------------------------------------
__device__ __forceinline__ uint32_t smem_u32(const void* p) {
    uint32_t a;
    asm("{ .reg .u64 t; cvta.to.shared.u64 t, %1; cvt.u32.u64 %0, t; }" : "=r"(a) : "l"(p));
    return a;
}
__device__ __forceinline__ void cpasync16(uint32_t dst, const void* src) {
    asm volatile("cp.async.cg.shared.global [%0], [%1], 16;" :: "r"(dst), "l"(src));
}
#define CP_COMMIT() asm volatile("cp.async.commit_group;" ::: "memory")
#define CP_WAIT1()  asm volatile("cp.async.wait_group 1;" ::: "memory")

__device__ __forceinline__ void ldsm_x4(uint32_t* r, uint32_t addr) {
    asm volatile("ldmatrix.sync.aligned.m8n8.x4.shared.b16 {%0,%1,%2,%3}, [%4];"
                 : "=r"(r[0]), "=r"(r[1]), "=r"(r[2]), "=r"(r[3]) : "r"(addr));
}
__device__ __forceinline__ void mma16816(float* c, const uint32_t* a, const uint32_t* b) {
    asm volatile(
        "mma.sync.aligned.m16n8k16.row.col.f32.bf16.bf16.f32 "
        "{%0,%1,%2,%3}, {%4,%5,%6,%7}, {%8,%9}, {%0,%1,%2,%3};"
        : "+f"(c[0]), "+f"(c[1]), "+f"(c[2]), "+f"(c[3])
        : "r"(a[0]), "r"(a[1]), "r"(a[2]), "r"(a[3]), "r"(b[0]), "r"(b[1]));
}

// ---------------------------------------------------------------------------
// Prep: fp32 -> bf16 hi/lo split (elementwise). WHICH: 0=Q, 1=K
// ---------------------------------------------------------------------------
template <int WHICH>
__global__ __launch_bounds__(256)
void split_hl(const float4* __restrict__ in, int n4) {
    int i = blockIdx.x * 256 + threadIdx.x;
    if (i >= n4) return;
    __nv_bfloat16* hi = (WHICH == 0) ? g_Qh : g_Kh;
    __nv_bfloat16* lo = (WHICH == 0) ? g_Ql : g_Kl;
    float4 v = in[i];
    __nv_bfloat16 h0 = __float2bfloat16_rn(v.x), h1 = __float2bfloat16_rn(v.y),
                  h2 = __float2bfloat16_rn(v.z), h3 = __float2bfloat16_rn(v.w);
    __nv_bfloat16 l0 = __float2bfloat16_rn(v.x - __bfloat162float(h0));
    __nv_bfloat16 l1 = __float2bfloat16_rn(v.y - __bfloat162float(h1));
    __nv_bfloat16 l2 = __float2bfloat16_rn(v.z - __bfloat162float(h2));
    __nv_bfloat16 l3 = __float2bfloat16_rn(v.w - __bfloat162float(h3));
    __nv_bfloat162 ph0 = __halves2bfloat162(h0, h1), ph1 = __halves2bfloat162(h2, h3);
    __nv_bfloat162 pl0 = __halves2bfloat162(l0, l1), pl1 = __halves2bfloat162(l2, l3);
    *(uint2*)(hi + (size_t)i * 4) = make_uint2(*(uint32_t*)&ph0, *(uint32_t*)&ph1);
    *(uint2*)(lo + (size_t)i * 4) = make_uint2(*(uint32_t*)&pl0, *(uint32_t*)&pl1);
}

// ---------------------------------------------------------------------------
// Prep: V transpose + split:  g_Vt*[b][n][k] = split(V[b][k][n])
// ---------------------------------------------------------------------------
__global__ __launch_bounds__(256)
void transpose_split_v(const float* __restrict__ V) {
    __shared__ float t[32][33];
    const int b = blockIdx.z;
    const int n0 = blockIdx.x * 32, k0 = blockIdx.y * 32;
    const float* Vb = V + (size_t)b * LK * DD;
    for (int i = threadIdx.y; i < 32; i += 8)
        t[i][threadIdx.x] = Vb[(size_t)(k0 + i) * DD + n0 + threadIdx.x];
    __syncthreads();
    for (int i = threadIdx.y; i < 32; i += 8) {
        float v = t[threadIdx.x][i];
        __nv_bfloat16 h = __float2bfloat16_rn(v);
        __nv_bfloat16 l = __float2bfloat16_rn(v - __bfloat162float(h));
        size_t o = ((size_t)b * DD + n0 + i) * LK + k0 + threadIdx.x;
        g_Vth[o] = h;
        g_Vtl[o] = l;
    }
}

// ---------------------------------------------------------------------------
// Softmax over LK=2048, reading g_S, writing split P (bf16 hi/lo)
// ---------------------------------------------------------------------------
__global__ __launch_bounds__(256)
void softmax_split() {
    const int q = blockIdx.x, b = blockIdx.y;
    const size_t ro = ((size_t)b * LQ + q) * LK;
    const float* row = g_S + ro;
    const int tid = threadIdx.x;
    __shared__ float red[8];

    float vals[8];
    float m = NEG_INF;
#pragma unroll
    for (int i = 0; i < 8; i++) {
        vals[i] = row[tid + i * 256];
        m = fmaxf(m, vals[i]);
    }
#pragma unroll
    for (int off = 16; off > 0; off >>= 1)
        m = fmaxf(m, __shfl_xor_sync(0xffffffffu, m, off));
    if ((tid & 31) == 0) red[tid >> 5] = m;
    __syncthreads();
    float mf = red[0];
#pragma unroll
    for (int w = 1; w < 8; w++) mf = fmaxf(mf, red[w]);
    __syncthreads();

    float s = 0.0f;
#pragma unroll
    for (int i = 0; i < 8; i++) {
        vals[i] = expf(vals[i] - mf);
        s += vals[i];
    }
#pragma unroll
    for (int off = 16; off > 0; off >>= 1)
        s += __shfl_xor_sync(0xffffffffu, s, off);
    if ((tid & 31) == 0) red[tid >> 5] = s;
    __syncthreads();
    float tot = 0.0f;
#pragma unroll
    for (int w = 0; w < 8; w++) tot += red[w];

    const float inv = 1.0f / tot;
#pragma unroll
    for (int i = 0; i < 8; i++) {
        float p = vals[i] * inv;
        __nv_bfloat16 h = __float2bfloat16_rn(p);
        __nv_bfloat16 l = __float2bfloat16_rn(p - __bfloat162float(h));
        g_Ph[ro + tid + i * 256] = h;
        g_Pl[ro + tid + i * 256] = l;
    }
}

// ---------------------------------------------------------------------------
// GEMM on mma.sync: C[2048,NTOT] = A[2048,KDIM] * B[NTOT,KDIM]^T per batch.
// Pre-split bf16 hi/lo, 3-term (AhBh + AhBl + AlBh).
// CTA 128(M) x 256(N) x 64(K); 8 warps = 2M x 4N, warp tile 64x64.
// Rationale (R11 profile): smem BW was the roof (LDSM bytes/MMA too high at
// warp tile 64x32). 64x64 tile: per-SM per-ks tensor 768cyc > smem 688cyc.
// 2-stage cp.async pipeline, 96KB/stage. No fragment double-buffer (regs).
// key_len skips (bit-exact): GEMM0 fully-masked N-tile -> NEG_INF fill only;
// GEMM1 K-trip truncated to ceil(klen/64) (klen==0 -> full: P uniform).
// ---------------------------------------------------------------------------
constexpr int STAGE_B = 98304;               // A 32KB + B 64KB
constexpr int SMEM_BYTES = 2 * STAGE_B;      // 192 KB
constexpr int OFF_B = 32768;

template <int KDIM>
__device__ __forceinline__ void load_stage_fn(
    uint32_t s0, const __nv_bfloat16* Ah, const __nv_bfloat16* Al,
    const __nv_bfloat16* Bh, const __nv_bfloat16* Bl, int k0, int tid) {
    // A: 128 rows x 64 k, hi+lo (4 chunks each per thread)
#pragma unroll
    for (int p = 0; p < 4; p++) {
        int lin = p * 256 + tid;
        int row = lin >> 3, ch = lin & 7;
        uint32_t d = s0 + (uint32_t)(row * 128) + (uint32_t)((ch ^ (row & 7)) << 4);
        size_t g = (size_t)row * KDIM + k0 + ch * 8;
        cpasync16(d,           Ah + g);
        cpasync16(d + 16384u,  Al + g);
    }
    // B: 256 rows x 64 k, hi+lo (8 chunks each per thread)
#pragma unroll
    for (int p = 0; p < 8; p++) {
        int lin = p * 256 + tid;
        int row = lin >> 3, ch = lin & 7;
        uint32_t d = s0 + OFF_B + (uint32_t)(row * 128) + (uint32_t)((ch ^ (row & 7)) << 4);
        size_t g = (size_t)row * KDIM + k0 + ch * 8;
        cpasync16(d,           Bh + g);
        cpasync16(d + 32768u,  Bl + g);
    }
}

struct Frags {
    uint32_t ah[4][4], al[4][4], bh[8][2], bl[8][2];
};

__device__ __forceinline__ void load_frags(
    Frags& f, uint32_t aB, uint32_t bB, int ks,
    uint32_t roff, int kx, int swz, int wm, int wn) {
    const uint32_t ksw = (uint32_t)((((ks * 2 + kx) ^ swz)) << 4);
#pragma unroll
    for (int i = 0; i < 4; i++) {
        uint32_t ad = aB + ((uint32_t)(wm * 64 + i * 16) << 7) + roff + ksw;
        ldsm_x4(f.ah[i], ad);
        ldsm_x4(f.al[i], ad + 16384u);
    }
#pragma unroll
    for (int jp = 0; jp < 4; jp++) {
        uint32_t bd = bB + ((uint32_t)(wn * 64 + jp * 16) << 7) + roff + ksw;
        uint32_t t[4];
        ldsm_x4(t, bd);
        f.bh[jp * 2][0] = t[0]; f.bh[jp * 2][1] = t[2];
        f.bh[jp * 2 + 1][0] = t[1]; f.bh[jp * 2 + 1][1] = t[3];
        ldsm_x4(t, bd + 32768u);
        f.bl[jp * 2][0] = t[0]; f.bl[jp * 2][1] = t[2];
        f.bl[jp * 2 + 1][0] = t[1]; f.bl[jp * 2 + 1][1] = t[3];
    }
}

// Term-major issue: 32 acc tiles per term -> same-acc RAW distance = 32.
__device__ __forceinline__ void mma_all(float acc[4][8][4], const Frags& f) {
#pragma unroll
    for (int i = 0; i < 4; i++)
#pragma unroll
        for (int j = 0; j < 8; j++)
            mma16816(acc[i][j], f.ah[i], f.bh[j]);
#pragma unroll
    for (int i = 0; i < 4; i++)
#pragma unroll
        for (int j = 0; j < 8; j++)
            mma16816(acc[i][j], f.ah[i], f.bl[j]);
#pragma unroll
    for (int i = 0; i < 4; i++)
#pragma unroll
        for (int j = 0; j < 8; j++)
            mma16816(acc[i][j], f.al[i], f.bh[j]);
}

template <int WHICH>
__global__ __launch_bounds__(256, 1)
void gemm_mma(float* __restrict__ OutArg, const int* __restrict__ key_len) {
    constexpr int KDIM = (WHICH == 0) ? 1024 : 2048;
    constexpr int NTOT = (WHICH == 0) ? 2048 : 1024;
    constexpr bool MASK = (WHICH == 0);
    constexpr int KITERS = KDIM / 64;

    extern __shared__ __align__(1024) char sm[];
    const uint32_t sb = smem_u32(sm);

    const int tid = threadIdx.x, lane = tid & 31, warp = tid >> 5;
    const int wm = warp >> 2, wn = warp & 3;
    const int b = blockIdx.z, m0 = blockIdx.y * 128, n0 = blockIdx.x * 256;
    const int klen = key_len[b];

    const __nv_bfloat16 *Ah, *Al, *Bh, *Bl;
    float* C;
    if (WHICH == 0) { Ah = g_Qh; Al = g_Ql; Bh = g_Kh; Bl = g_Kl; C = g_S; }
    else            { Ah = g_Ph; Al = g_Pl; Bh = g_Vth; Bl = g_Vtl; C = OutArg; }
    C += (size_t)b * 2048 * NTOT;

    // GEMM0: fully-masked 256-wide tile -> pure NEG_INF fill.
    if (MASK && n0 >= klen) {
        const float4 nf = make_float4(NEG_INF, NEG_INF, NEG_INF, NEG_INF);
#pragma unroll
        for (int p = 0; p < 32; p++) {
            int idx = p * 256 + tid;          // 8192 float4s = 128x256
            int row = idx >> 6, c4 = idx & 63;
            *(float4*)(C + (size_t)(m0 + row) * NTOT + n0 + c4 * 4) = nf;
        }
        return;
    }

    // GEMM1: truncate K-trip to nonzero P columns (bit-exact).
    int kiters = KITERS;
    if (!MASK && klen > 0) {
        int needed = (klen + 63) >> 6;
        kiters = needed < KITERS ? needed : KITERS;
    }

    Ah += (size_t)b * 2048 * KDIM + (size_t)m0 * KDIM;
    Al += (size_t)b * 2048 * KDIM + (size_t)m0 * KDIM;
    Bh += (size_t)b * NTOT * KDIM + (size_t)n0 * KDIM;
    Bl += (size_t)b * NTOT * KDIM + (size_t)n0 * KDIM;

    float acc[4][8][4];
#pragma unroll
    for (int i = 0; i < 4; i++)
#pragma unroll
        for (int j = 0; j < 8; j++)
#pragma unroll
            for (int k = 0; k < 4; k++) acc[i][j][k] = 0.0f;

    const int lrow = lane & 7, sub = lane >> 3;
    const uint32_t roff = (uint32_t)((lrow + ((sub & 1) << 3)) << 7);
    const int kx = sub >> 1;
    const int swz = lrow;

    // 2-stage pipeline: prologue loads stage 0
    load_stage_fn<KDIM>(sb, Ah, Al, Bh, Bl, 0, tid);
    CP_COMMIT();

    Frags fr;
    for (int it = 0; it < kiters; ++it) {
        if (it + 1 < kiters)
            load_stage_fn<KDIM>(sb + ((it + 1) & 1) * STAGE_B, Ah, Al, Bh, Bl,
                                (it + 1) * 64, tid);
        CP_COMMIT();
        CP_WAIT1();            // stage it resident (it+1 may pend)
        __syncthreads();

        const uint32_t aB = sb + (uint32_t)((it & 1) * STAGE_B);
        const uint32_t bB = aB + OFF_B;
#pragma unroll
        for (int ks = 0; ks < 4; ++ks) {
            load_frags(fr, aB, bB, ks, roff, kx, swz, wm, wn);
            mma_all(acc, fr);
        }
        __syncthreads();       // all reads of stage it done before it+2 overwrite
    }

    // Epilogue: float2 stores, mask for GEMM0 partial tiles
    const int kl = MASK ? klen : 0x7fffffff;
#pragma unroll
    for (int i = 0; i < 4; i++) {
        const int r = m0 + wm * 64 + i * 16 + (lane >> 2);
#pragma unroll
        for (int j = 0; j < 8; j++) {
            const int col = n0 + wn * 64 + j * 8 + ((lane & 3) << 1);
            float2 v0 = make_float2(acc[i][j][0], acc[i][j][1]);
            float2 v1 = make_float2(acc[i][j][2], acc[i][j][3]);
            if (MASK) {
                if (col     >= kl) { v0.x = NEG_INF; v1.x = NEG_INF; }
                if (col + 1 >= kl) { v0.y = NEG_INF; v1.y = NEG_INF; }
            }
            *(float2*)(C + (size_t)r * NTOT + col) = v0;
            *(float2*)(C + (size_t)(r + 8) * NTOT + col) = v1;
        }
    }
}

// ---------------------------------------------------------------------------
extern "C" void kernel_launch(void* const* d_in, const int* in_sizes, int n_in,
                              void* d_out, int out_size) {
    const float* Q      = (const float*)d_in[0];
    const float* K      = (const float*)d_in[1];
    const float* V      = (const float*)d_in[2];
    const int*  key_len = (const int*)d_in[3];
    float* Out = (float*)d_out;

    cudaFuncSetAttribute(gemm_mma<0>, cudaFuncAttributeMaxDynamicSharedMemorySize, SMEM_BYTES);
    cudaFuncSetAttribute(gemm_mma<1>, cudaFuncAttributeMaxDynamicSharedMemorySize, SMEM_BYTES);

    const int n4 = Bc * LQ * DD / 4;    // 8388608
    split_hl<0><<<(n4 + 255) / 256, 256>>>((const float4*)Q, n4);
    split_hl<1><<<(n4 + 255) / 256, 256>>>((const float4*)K, n4);

    dim3 gt(DD / 32, LK / 32, Bc);
    transpose_split_v<<<gt, dim3(32, 8)>>>(V);

    dim3 g1(LK / 256, LQ / 128, Bc);    // (8,16,16)
    gemm_mma<0><<<g1, 256, SMEM_BYTES>>>(nullptr, key_len);

    dim3 g2(LQ, Bc);
    softmax_split<<<g2, 256>>>();

    dim3 g3(DD / 256, LQ / 128, Bc);    // (4,16,16)
    gemm_mma<1><<<g3, 256, SMEM_BYTES>>>(Out, key_len);
}

// round 16
// speedup vs baseline: 1.0559x; 1.0559x over previous
#include <cuda_runtime.h>
#include <cuda_bf16.h>
#include <cstdint>

#define NEG_INF (-3.402823466e38f)

constexpr int Bc = 16, LQ = 2048, LK = 2048, DD = 1024;

// Static device scratch (sanctioned alloc-free path)
__device__ float g_S[(size_t)Bc * LQ * LK];                                  // 268 MB
__device__ __nv_bfloat16 g_Qh[(size_t)Bc * LQ * DD], g_Ql[(size_t)Bc * LQ * DD];
__device__ __nv_bfloat16 g_Kh[(size_t)Bc * LK * DD], g_Kl[(size_t)Bc * LK * DD];
__device__ __nv_bfloat16 g_Vth[(size_t)Bc * DD * LK], g_Vtl[(size_t)Bc * DD * LK];
__device__ __nv_bfloat16 g_Ph[(size_t)Bc * LQ * LK], g_Pl[(size_t)Bc * LQ * LK];

// ---------------------------------------------------------------------------
// Base-ISA helpers
// ---------------------------------------------------------------------------
__device__ __forceinline__ uint32_t smem_u32(const void* p) {
    uint32_t a;
    asm("{ .reg .u64 t; cvta.to.shared.u64 t, %1; cvt.u32.u64 %0, t; }" : "=r"(a) : "l"(p));
    return a;
}
__device__ __forceinline__ void cpasync16(uint32_t dst, const void* src) {
    asm volatile("cp.async.cg.shared.global [%0], [%1], 16;" :: "r"(dst), "l"(src));
}
#define CP_COMMIT() asm volatile("cp.async.commit_group;" ::: "memory")
#define CP_WAIT1()  asm volatile("cp.async.wait_group 1;" ::: "memory")

__device__ __forceinline__ void ldsm_x4(uint32_t* r, uint32_t addr) {
    asm volatile("ldmatrix.sync.aligned.m8n8.x4.shared.b16 {%0,%1,%2,%3}, [%4];"
                 : "=r"(r[0]), "=r"(r[1]), "=r"(r[2]), "=r"(r[3]) : "r"(addr));
}
__device__ __forceinline__ void mma16816(float* c, const uint32_t* a, const uint32_t* b) {
    asm volatile(
        "mma.sync.aligned.m16n8k16.row.col.f32.bf16.bf16.f32 "
        "{%0,%1,%2,%3}, {%4,%5,%6,%7}, {%8,%9}, {%0,%1,%2,%3};"
        : "+f"(c[0]), "+f"(c[1]), "+f"(c[2]), "+f"(c[3])
        : "r"(a[0]), "r"(a[1]), "r"(a[2]), "r"(a[3]), "r"(b[0]), "r"(b[1]));
}

// ---------------------------------------------------------------------------
// Prep: fp32 -> bf16 hi/lo split (elementwise). WHICH: 0=Q, 1=K
// ---------------------------------------------------------------------------
template <int WHICH>
__global__ __launch_bounds__(256)
void split_hl(const float4* __restrict__ in, int n4) {
    int i = blockIdx.x * 256 + threadIdx.x;
    if (i >= n4) return;
    __nv_bfloat16* hi = (WHICH == 0) ? g_Qh : g_Kh;
    __nv_bfloat16* lo = (WHICH == 0) ? g_Ql : g_Kl;
    float4 v = in[i];
    __nv_bfloat16 h0 = __float2bfloat16_rn(v.x), h1 = __float2bfloat16_rn(v.y),
                  h2 = __float2bfloat16_rn(v.z), h3 = __float2bfloat16_rn(v.w);
    __nv_bfloat16 l0 = __float2bfloat16_rn(v.x - __bfloat162float(h0));
    __nv_bfloat16 l1 = __float2bfloat16_rn(v.y - __bfloat162float(h1));
    __nv_bfloat16 l2 = __float2bfloat16_rn(v.z - __bfloat162float(h2));
    __nv_bfloat16 l3 = __float2bfloat16_rn(v.w - __bfloat162float(h3));
    __nv_bfloat162 ph0 = __halves2bfloat162(h0, h1), ph1 = __halves2bfloat162(h2, h3);
    __nv_bfloat162 pl0 = __halves2bfloat162(l0, l1), pl1 = __halves2bfloat162(l2, l3);
    *(uint2*)(hi + (size_t)i * 4) = make_uint2(*(uint32_t*)&ph0, *(uint32_t*)&ph1);
    *(uint2*)(lo + (size_t)i * 4) = make_uint2(*(uint32_t*)&pl0, *(uint32_t*)&pl1);
}

// ---------------------------------------------------------------------------
// Prep: V transpose + split:  g_Vt*[b][n][k] = split(V[b][k][n])
// ---------------------------------------------------------------------------
__global__ __launch_bounds__(256)
void transpose_split_v(const float* __restrict__ V) {
    __shared__ float t[32][33];
    const int b = blockIdx.z;
    const int n0 = blockIdx.x * 32, k0 = blockIdx.y * 32;
    const float* Vb = V + (size_t)b * LK * DD;
    for (int i = threadIdx.y; i < 32; i += 8)
        t[i][threadIdx.x] = Vb[(size_t)(k0 + i) * DD + n0 + threadIdx.x];
    __syncthreads();
    for (int i = threadIdx.y; i < 32; i += 8) {
        float v = t[threadIdx.x][i];
        __nv_bfloat16 h = __float2bfloat16_rn(v);
        __nv_bfloat16 l = __float2bfloat16_rn(v - __bfloat162float(h));
        size_t o = ((size_t)b * DD + n0 + i) * LK + k0 + threadIdx.x;
        g_Vth[o] = h;
        g_Vtl[o] = l;
    }
}

// ---------------------------------------------------------------------------
// Softmax over LK=2048, reading g_S, writing split P (bf16 hi/lo)
// ---------------------------------------------------------------------------
__global__ __launch_bounds__(256)
void softmax_split() {
    const int q = blockIdx.x, b = blockIdx.y;
    const size_t ro = ((size_t)b * LQ + q) * LK;
    const float* row = g_S + ro;
    const int tid = threadIdx.x;
    __shared__ float red[8];

    float vals[8];
    float m = NEG_INF;
#pragma unroll
    for (int i = 0; i < 8; i++) {
        vals[i] = row[tid + i * 256];
        m = fmaxf(m, vals[i]);
    }
#pragma unroll
    for (int off = 16; off > 0; off >>= 1)
        m = fmaxf(m, __shfl_xor_sync(0xffffffffu, m, off));
    if ((tid & 31) == 0) red[tid >> 5] = m;
    __syncthreads();
    float mf = red[0];
#pragma unroll
    for (int w = 1; w < 8; w++) mf = fmaxf(mf, red[w]);
    __syncthreads();

    float s = 0.0f;
#pragma unroll
    for (int i = 0; i < 8; i++) {
        vals[i] = expf(vals[i] - mf);
        s += vals[i];
    }
#pragma unroll
    for (int off = 16; off > 0; off >>= 1)
        s += __shfl_xor_sync(0xffffffffu, s, off);
    if ((tid & 31) == 0) red[tid >> 5] = s;
    __syncthreads();
    float tot = 0.0f;
#pragma unroll
    for (int w = 0; w < 8; w++) tot += red[w];

    const float inv = 1.0f / tot;
#pragma unroll
    for (int i = 0; i < 8; i++) {
        float p = vals[i] * inv;
        __nv_bfloat16 h = __float2bfloat16_rn(p);
        __nv_bfloat16 l = __float2bfloat16_rn(p - __bfloat162float(h));
        g_Ph[ro + tid + i * 256] = h;
        g_Pl[ro + tid + i * 256] = l;
    }
}

// ---------------------------------------------------------------------------
// GEMM on mma.sync: C[2048,NTOT] = A[2048,KDIM] * B[NTOT,KDIM]^T per batch.
// Pre-split bf16 hi/lo, 3-term (AhBh + AhBl + AlBh).
// Occupancy experiment: CTA 128x128xBK32, warp tile 64x32, 8 warps,
// 3-stage pipeline @ 32KB/stage = 96KB smem, <=128 regs => 2 CTAs/SM
// (16 warps, 4/SMSP). All measured configs had 8 warps/SM and tensor pinned
// at ~60% regardless of smem ratio or issue order -> test warp concurrency.
// 64B-row swizzle: chunk ^= (row>>1)&3 (conflict-free cp.async + LDSM).
// key_len skips (bit-exact) as R11.
// ---------------------------------------------------------------------------
constexpr int STAGE_B = 32768;               // Ah 8K | Al 8K | Bh 8K | Bl 8K
constexpr int NSTAGE = 3;
constexpr int SMEM_BYTES = NSTAGE * STAGE_B; // 96 KB
constexpr int OF_AL = 8192, OF_BH = 16384, OF_BL = 24576;

// Swizzled byte offset for (row, 16B-chunk c) in a 128x32-bf16 (64B-row) tile
__device__ __forceinline__ uint32_t sw64(int row, int c) {
    return (uint32_t)(row * 64) + (uint32_t)((c ^ ((row >> 1) & 3)) << 4);
}

template <int KDIM>
__device__ __forceinline__ void load_stage_fn(
    uint32_t s0, const __nv_bfloat16* Ah, const __nv_bfloat16* Al,
    const __nv_bfloat16* Bh, const __nv_bfloat16* Bl, int k0, int tid) {
    // each sub-tile: 128 rows x 4 chunks = 512 chunks; 2 per thread
#pragma unroll
    for (int p = 0; p < 2; p++) {
        int lin = p * 256 + tid;
        int row = lin >> 2, c = lin & 3;
        uint32_t d = s0 + sw64(row, c);
        size_t g = (size_t)row * KDIM + k0 + c * 8;
        cpasync16(d,         Ah + g);
        cpasync16(d + OF_AL, Al + g);
        cpasync16(d + OF_BH, Bh + g);
        cpasync16(d + OF_BL, Bl + g);
    }
}

template <int WHICH>
__global__ __launch_bounds__(256, 2)
void gemm_mma(float* __restrict__ OutArg, const int* __restrict__ key_len) {
    constexpr int KDIM = (WHICH == 0) ? 1024 : 2048;
    constexpr int NTOT = (WHICH == 0) ? 2048 : 1024;
    constexpr bool MASK = (WHICH == 0);
    constexpr int KITERS = KDIM / 32;

    extern __shared__ __align__(1024) char sm[];
    const uint32_t sb = smem_u32(sm);

    const int tid = threadIdx.x, lane = tid & 31, warp = tid >> 5;
    const int wm = warp >> 2, wn = warp & 3;
    const int b = blockIdx.z, m0 = blockIdx.y * 128, n0 = blockIdx.x * 128;
    const int klen = key_len[b];

    const __nv_bfloat16 *Ah, *Al, *Bh, *Bl;
    float* C;
    if (WHICH == 0) { Ah = g_Qh; Al = g_Ql; Bh = g_Kh; Bl = g_Kl; C = g_S; }
    else            { Ah = g_Ph; Al = g_Pl; Bh = g_Vth; Bl = g_Vtl; C = OutArg; }
    C += (size_t)b * 2048 * NTOT;

    // GEMM0: fully-masked 128-wide tile -> pure NEG_INF fill.
    if (MASK && n0 >= klen) {
        const float4 nf = make_float4(NEG_INF, NEG_INF, NEG_INF, NEG_INF);
#pragma unroll
        for (int p = 0; p < 16; p++) {
            int idx = p * 256 + tid;          // 4096 float4s = 128x128
            int row = idx >> 5, c4 = idx & 31;
            *(float4*)(C + (size_t)(m0 + row) * NTOT + n0 + c4 * 4) = nf;
        }
        return;
    }

    // GEMM1: truncate K-trip to nonzero P columns (bit-exact).
    int kiters = KITERS;
    if (!MASK && klen > 0) {
        int needed = (klen + 31) >> 5;
        kiters = needed < KITERS ? needed : KITERS;
    }

    Ah += (size_t)b * 2048 * KDIM + (size_t)m0 * KDIM;
    Al += (size_t)b * 2048 * KDIM + (size_t)m0 * KDIM;
    Bh += (size_t)b * NTOT * KDIM + (size_t)n0 * KDIM;
    Bl += (size_t)b * NTOT * KDIM + (size_t)n0 * KDIM;

    float acc[4][4][4];
#pragma unroll
    for (int i = 0; i < 4; i++)
#pragma unroll
        for (int j = 0; j < 4; j++)
#pragma unroll
            for (int k = 0; k < 4; k++) acc[i][j][k] = 0.0f;

    // ldmatrix lane components: row-in-tile = lane&15, chunk offset = lane>>4
    const int lrow16 = lane & 15;
    const int lkx = lane >> 4;

    // Prologue: stages 0 and 1 in flight
    load_stage_fn<KDIM>(sb,           Ah, Al, Bh, Bl, 0,  tid);
    CP_COMMIT();
    load_stage_fn<KDIM>(sb + STAGE_B, Ah, Al, Bh, Bl, 32, tid);
    CP_COMMIT();

    for (int it = 0; it < kiters; ++it) {
        CP_WAIT1();            // stage it resident (it+1 may pend)
        __syncthreads();       // readers of stage (it+2)%3 (iter it-1) done
        if (it + 2 < kiters)
            load_stage_fn<KDIM>(sb + ((it + 2) % 3) * STAGE_B, Ah, Al, Bh, Bl,
                                (it + 2) * 32, tid);
        CP_COMMIT();           // possibly-empty commit keeps group indices aligned

        const uint32_t st = sb + (uint32_t)((it % 3) * STAGE_B);
#pragma unroll
        for (int ks = 0; ks < 2; ++ks) {
            const int cb = ks * 2;
            // A-hi + B-hi, then hh term
            uint32_t ah[4][4], bh[4][2];
#pragma unroll
            for (int i = 0; i < 4; i++) {
                int r = wm * 64 + i * 16 + lrow16;
                ldsm_x4(ah[i], st + sw64(r, cb + lkx));
            }
#pragma unroll
            for (int jp = 0; jp < 2; jp++) {
                int r = wn * 32 + jp * 16 + lrow16;
                uint32_t t[4];
                ldsm_x4(t, st + OF_BH + sw64(r, cb + lkx));
                bh[jp * 2][0] = t[0]; bh[jp * 2][1] = t[2];
                bh[jp * 2 + 1][0] = t[1]; bh[jp * 2 + 1][1] = t[3];
            }
#pragma unroll
            for (int i = 0; i < 4; i++)
#pragma unroll
                for (int j = 0; j < 4; j++)
                    mma16816(acc[i][j], ah[i], bh[j]);
            // B-lo, then hl term
            {
                uint32_t bl[4][2];
#pragma unroll
                for (int jp = 0; jp < 2; jp++) {
                    int r = wn * 32 + jp * 16 + lrow16;
                    uint32_t t[4];
                    ldsm_x4(t, st + OF_BL + sw64(r, cb + lkx));
                    bl[jp * 2][0] = t[0]; bl[jp * 2][1] = t[2];
                    bl[jp * 2 + 1][0] = t[1]; bl[jp * 2 + 1][1] = t[3];
                }
#pragma unroll
                for (int i = 0; i < 4; i++)
#pragma unroll
                    for (int j = 0; j < 4; j++)
                        mma16816(acc[i][j], ah[i], bl[j]);
            }
            // A-lo, then lh term
            {
                uint32_t al[4][4];
#pragma unroll
                for (int i = 0; i < 4; i++) {
                    int r = wm * 64 + i * 16 + lrow16;
                    ldsm_x4(al[i], st + OF_AL + sw64(r, cb + lkx));
                }
#pragma unroll
                for (int i = 0; i < 4; i++)
#pragma unroll
                    for (int j = 0; j < 4; j++)
                        mma16816(acc[i][j], al[i], bh[j]);
            }
        }
    }

    // Epilogue: float2 stores, mask for GEMM0 partial tiles
    const int kl = MASK ? klen : 0x7fffffff;
#pragma unroll
    for (int i = 0; i < 4; i++) {
        const int r = m0 + wm * 64 + i * 16 + (lane >> 2);
#pragma unroll
        for (int j = 0; j < 4; j++) {
            const int col = n0 + wn * 32 + j * 8 + ((lane & 3) << 1);
            float2 v0 = make_float2(acc[i][j][0], acc[i][j][1]);
            float2 v1 = make_float2(acc[i][j][2], acc[i][j][3]);
            if (MASK) {
                if (col     >= kl) { v0.x = NEG_INF; v1.x = NEG_INF; }
                if (col + 1 >= kl) { v0.y = NEG_INF; v1.y = NEG_INF; }
            }
            *(float2*)(C + (size_t)r * NTOT + col) = v0;
            *(float2*)(C + (size_t)(r + 8) * NTOT + col) = v1;
        }
    }
}

// ---------------------------------------------------------------------------
extern "C" void kernel_launch(void* const* d_in, const int* in_sizes, int n_in,
                              void* d_out, int out_size) {
    const float* Q      = (const float*)d_in[0];
    const float* K      = (const float*)d_in[1];
    const float* V      = (const float*)d_in[2];
    const int*  key_len = (const int*)d_in[3];
    float* Out = (float*)d_out;

    cudaFuncSetAttribute(gemm_mma<0>, cudaFuncAttributeMaxDynamicSharedMemorySize, SMEM_BYTES);
    cudaFuncSetAttribute(gemm_mma<1>, cudaFuncAttributeMaxDynamicSharedMemorySize, SMEM_BYTES);

    const int n4 = Bc * LQ * DD / 4;    // 8388608
    split_hl<0><<<(n4 + 255) / 256, 256>>>((const float4*)Q, n4);
    split_hl<1><<<(n4 + 255) / 256, 256>>>((const float4*)K, n4);

    dim3 gt(DD / 32, LK / 32, Bc);
    transpose_split_v<<<gt, dim3(32, 8)>>>(V);

    dim3 g1(LK / 128, LQ / 128, Bc);    // (16,16,16)
    gemm_mma<0><<<g1, 256, SMEM_BYTES>>>(nullptr, key_len);

    dim3 g2(LQ, Bc);
    softmax_split<<<g2, 256>>>();

    dim3 g3(DD / 128, LQ / 128, Bc);    // (8,16,16)
    gemm_mma<1><<<g3, 256, SMEM_BYTES>>>(Out, key_len);
}